// round 10
// baseline (speedup 1.0000x reference)
#include <cuda_runtime.h>
#include <cuda_fp16.h>
#include <cstdint>

// ---------------- problem dims ----------------
#define S_DIM 1024
#define B_DIM 64
#define M_TOT 65536           // S*B
#define QK_DIM 1024
#define KK 2048               // concatenated K = 2*QK
#define H_DIM 1024
#define DV_DIM 1024

// ---------------- GEMM tiling ----------------
#define MT 128
#define NT 256
#define KC 64                 // K halfs per stage
#define NSK (KK / KC)         // 32 k-stages
#define ROW_B 144             // smem row pitch bytes: 64 halfs + 8 pad halfs
#define A_BYTES (MT * ROW_B)             // 18432
#define B_BYTES (NT * ROW_B)             // 36864
#define STAGE_BYTES (A_BYTES + B_BYTES)  // 55296
#define SMEM_TILES_OFF 4096
#define SMEM_NEED (SMEM_TILES_OFF + 3 * STAGE_BYTES)   // 169984

#define OSB 16                // output s-blocks

// ---------------- device scratch (allocation-free) ----------------
__device__ __half g_W[(size_t)H_DIM * KK];    // packed [W_q|W_k] fp16 (4 MB)
__device__ float  g_part[4 * M_TOT];          // per-N-tile score partials
__device__ float  g_attn[M_TOT];
__device__ float  g_opart[OSB * B_DIM * DV_DIM]; // output partials (4 MB)

// ---------------- helpers ----------------
__device__ __forceinline__ uint32_t smem_u32(const void* p) {
    return (uint32_t)__cvta_generic_to_shared(p);
}

// fp16-accumulator MMA: D,C are 2x .f16x2 regs
__device__ __forceinline__ void mma16816_f16(uint32_t* c, const uint32_t* a,
                                             uint32_t b0, uint32_t b1) {
    asm volatile(
        "mma.sync.aligned.m16n8k16.row.col.f16.f16.f16.f16 "
        "{%0,%1}, {%2,%3,%4,%5}, {%6,%7}, {%0,%1};"
        : "+r"(c[0]), "+r"(c[1])
        : "r"(a[0]), "r"(a[1]), "r"(a[2]), "r"(a[3]), "r"(b0), "r"(b1));
}

__device__ __forceinline__ float fast_tanh(float x) {
    float e = __expf(-2.0f * fabsf(x));          // MUFU.EX2-based
    float r = __fdividef(1.0f - e, 1.0f + e);    // MUFU.RCP-based
    return copysignf(r, x);
}

// ---------------- Kernel 1: pack [W_q|W_k] -> fp16 ----------------
__global__ void __launch_bounds__(256) pack_W_kernel(const float4* __restrict__ wq,
                                                     const float4* __restrict__ wk) {
    const size_t n4 = (size_t)H_DIM * QK_DIM / 4;
    for (size_t i = (size_t)blockIdx.x * blockDim.x + threadIdx.x; i < n4;
         i += (size_t)gridDim.x * blockDim.x) {
        size_t h = i >> 8;
        size_t c = (i & 255) << 2;
        float4 qa = wq[i];
        float4 ka = wk[i];
        union { __half2 h2[2]; uint2 u; } pq, pk;
        pq.h2[0] = __floats2half2_rn(qa.x, qa.y);
        pq.h2[1] = __floats2half2_rn(qa.z, qa.w);
        pk.h2[0] = __floats2half2_rn(ka.x, ka.y);
        pk.h2[1] = __floats2half2_rn(ka.z, ka.w);
        *(uint2*)(&g_W[h * KK + c])          = pq.u;
        *(uint2*)(&g_W[h * KK + QK_DIM + c]) = pk.u;
    }
}

// ---------------- Kernel 2: GEMM(features) + tanh + w_v reduce -> score partials ----------------
// 256 threads = 8 warps, warp layout 2m x 4n, warp tile 64 x 64.
// fp16 accumulators, flushed to fp32 every 2 k-stages (K=128 chunks).
__global__ void __launch_bounds__(256, 1)
gemm_scores_kernel(const float* __restrict__ queries,
                   const float* __restrict__ keys,
                   const float* __restrict__ w_v) {
    extern __shared__ char smem[];
    float* sWv   = (float*)smem;                 // 256 floats
    float* sPart = (float*)(smem + 1024);        // 4*128 floats
    char*  tiles = smem + SMEM_TILES_OFF;

    const int tid  = threadIdx.x;
    const int wid  = tid >> 5;
    const int lane = tid & 31;
    const int wm   = wid & 1;        // warp m index (0..1) -> 64 rows each
    const int wn   = wid >> 1;       // warp n index (0..3) -> 64 cols each
    const int nt   = blockIdx.x;     // N tile (0..3), fastest varying: A reuse in L2
    const int m0   = blockIdx.y * MT;
    const int h0   = nt * NT;

    sWv[tid] = w_v[h0 + tid];

    float acc[4][8][4];
    uint32_t acch[4][8][2];
#pragma unroll
    for (int mf = 0; mf < 4; mf++)
#pragma unroll
        for (int nf = 0; nf < 8; nf++) {
#pragma unroll
            for (int i = 0; i < 4; i++) acc[mf][nf][i] = 0.f;
            acch[mf][nf][0] = 0u; acch[mf][nf][1] = 0u;
        }

    const int ar = tid >> 4;              // A base row (rows step by 16 per j)
    const int ac = tid & 15;              // float4 col within 64-float k-chunk

    float4 pre[8];

    auto ldg_A = [&](int s) {
        const int kc = (s < 16) ? s * KC : (s - 16) * KC;
        const float* src = (s < 16) ? queries : keys;
#pragma unroll
        for (int j = 0; j < 8; j++) {
            int r = ar + j * 16;
            pre[j] = *(const float4*)(src + (size_t)(m0 + r) * QK_DIM + kc + ac * 4);
        }
    };
    auto sts_A = [&](int buf) {
        char* As = tiles + buf * STAGE_BYTES;
#pragma unroll
        for (int j = 0; j < 8; j++) {
            int r = ar + j * 16;
            union { __half2 h2[2]; uint2 u; } p;
            p.h2[0] = __floats2half2_rn(pre[j].x, pre[j].y);
            p.h2[1] = __floats2half2_rn(pre[j].z, pre[j].w);
            *(uint2*)(As + r * ROW_B + ac * 8) = p.u;
        }
    };
    auto cp_B = [&](int s, int buf) {
        char* Bs = tiles + buf * STAGE_BYTES + A_BYTES;
        const int k0 = s * KC;
#pragma unroll
        for (int j = 0; j < 8; j++) {
            int i = tid + j * 256;
            int r = i >> 3, c = i & 7;
            uint32_t sb = smem_u32(Bs + r * ROW_B + c * 16);
            size_t gb = (size_t)__cvta_generic_to_global(
                g_W + (size_t)(h0 + r) * KK + k0 + c * 8);
            asm volatile("cp.async.cg.shared.global [%0], [%1], 16;" :: "r"(sb), "l"(gb));
        }
        asm volatile("cp.async.commit_group;" ::: "memory");
    };

    auto compute_stage = [&](int buf) {
        char* As = tiles + buf * STAGE_BYTES;
        char* Bs = As + A_BYTES;
#pragma unroll
        for (int ks = 0; ks < 4; ks++) {     // four k16 steps per 64-half stage
            uint32_t a[4][4];
#pragma unroll
            for (int mf = 0; mf < 4; mf++) {
                int row = wm * 64 + mf * 16 + (lane & 7) + (lane & 8);
                int kb  = ks * 32 + ((lane >= 16) ? 16 : 0);
                uint32_t addr = smem_u32(As + row * ROW_B + kb);
                asm volatile(
                    "ldmatrix.sync.aligned.m8n8.x4.shared.b16 {%0,%1,%2,%3}, [%4];"
                    : "=r"(a[mf][0]), "=r"(a[mf][1]), "=r"(a[mf][2]), "=r"(a[mf][3])
                    : "r"(addr));
            }
#pragma unroll
            for (int np = 0; np < 4; np++) { // each x4 covers 2 n-frags
                uint32_t b[4];
                int rn = wn * 64 + np * 16 + (lane & 7) + ((lane >= 16) ? 8 : 0);
                int kb = ks * 32 + ((lane & 8) ? 16 : 0);
                uint32_t addr = smem_u32(Bs + rn * ROW_B + kb);
                asm volatile(
                    "ldmatrix.sync.aligned.m8n8.x4.shared.b16 {%0,%1,%2,%3}, [%4];"
                    : "=r"(b[0]), "=r"(b[1]), "=r"(b[2]), "=r"(b[3])
                    : "r"(addr));
#pragma unroll
                for (int mf = 0; mf < 4; mf++) {
                    mma16816_f16(acch[mf][2 * np],     a[mf], b[0], b[1]);
                    mma16816_f16(acch[mf][2 * np + 1], a[mf], b[2], b[3]);
                }
            }
        }
    };

    // flush fp16 accumulators into fp32 and zero them
    auto flush = [&]() {
#pragma unroll
        for (int mf = 0; mf < 4; mf++)
#pragma unroll
            for (int nf = 0; nf < 8; nf++) {
                float2 lo = __half22float2(*(__half2*)&acch[mf][nf][0]);
                float2 hi = __half22float2(*(__half2*)&acch[mf][nf][1]);
                acc[mf][nf][0] += lo.x;
                acc[mf][nf][1] += lo.y;
                acc[mf][nf][2] += hi.x;
                acc[mf][nf][3] += hi.y;
                acch[mf][nf][0] = 0u;
                acch[mf][nf][1] = 0u;
            }
    };

    // ---- prologue: stages 0,1 in smem; stage 2 in registers ----
    ldg_A(0); sts_A(0); cp_B(0, 0);
    ldg_A(1); sts_A(1); cp_B(1, 1);
    ldg_A(2);

    // ---- main pipeline (3 smem buffers) ----
    for (int s = 0; s < NSK; s++) {
        if (s == NSK - 1) { asm volatile("cp.async.wait_group 0;" ::: "memory"); }
        else              { asm volatile("cp.async.wait_group 1;" ::: "memory"); }
        __syncthreads();
        if (s + 2 < NSK) {
            int buf = (s + 2) % 3;
            sts_A(buf);
            cp_B(s + 2, buf);
            if (s + 3 < NSK) ldg_A(s + 3);
        }
        compute_stage(s % 3);
        if (s & 1) flush();          // K=128 fp16 accumulation chunks
    }

    // ---- epilogue: score_partial[m] = sum_h tanh(feat[m,h]) * w_v[h] ----
    float s0[4] = {0.f, 0.f, 0.f, 0.f}, s1[4] = {0.f, 0.f, 0.f, 0.f};
#pragma unroll
    for (int mf = 0; mf < 4; mf++) {
#pragma unroll
        for (int nf = 0; nf < 8; nf++) {
            int colb = wn * 64 + nf * 8 + 2 * (lane & 3);
            float wv0 = sWv[colb], wv1 = sWv[colb + 1];
            s0[mf] += fast_tanh(acc[mf][nf][0]) * wv0 + fast_tanh(acc[mf][nf][1]) * wv1;
            s1[mf] += fast_tanh(acc[mf][nf][2]) * wv0 + fast_tanh(acc[mf][nf][3]) * wv1;
        }
    }
#pragma unroll
    for (int mf = 0; mf < 4; mf++) {
#pragma unroll
        for (int o = 1; o <= 2; o <<= 1) {
            s0[mf] += __shfl_xor_sync(0xFFFFFFFFu, s0[mf], o);
            s1[mf] += __shfl_xor_sync(0xFFFFFFFFu, s1[mf], o);
        }
    }
    __syncthreads();
    if ((lane & 3) == 0) {
#pragma unroll
        for (int mf = 0; mf < 4; mf++) {
            int r = wm * 64 + mf * 16 + (lane >> 2);
            sPart[wn * 128 + r]     = s0[mf];
            sPart[wn * 128 + r + 8] = s1[mf];
        }
    }
    __syncthreads();
    if (tid < 128) {
        float tot = sPart[tid] + sPart[128 + tid] + sPart[256 + tid] + sPart[384 + tid];
        g_part[nt * M_TOT + m0 + tid] = tot;
    }
}

// ---------------- Kernel 3: softmax over S (per b column) ----------------
__global__ void __launch_bounds__(256) softmax_kernel() {
    int b = blockIdx.x, t = threadIdx.x;
    int wid = t >> 5, lid = t & 31;
    __shared__ float sm1[8], sm2[8];
    float v[4];
    float mx = -1e30f;
#pragma unroll
    for (int j = 0; j < 4; j++) {
        int m = (j * 256 + t) * B_DIM + b;
        v[j] = g_part[m] + g_part[M_TOT + m] + g_part[2 * M_TOT + m] + g_part[3 * M_TOT + m];
        mx = fmaxf(mx, v[j]);
    }
#pragma unroll
    for (int o = 16; o; o >>= 1) mx = fmaxf(mx, __shfl_xor_sync(0xFFFFFFFFu, mx, o));
    if (lid == 0) sm1[wid] = mx;
    __syncthreads();
    mx = sm1[0];
#pragma unroll
    for (int w = 1; w < 8; w++) mx = fmaxf(mx, sm1[w]);

    float e[4];
    float sum = 0.f;
#pragma unroll
    for (int j = 0; j < 4; j++) { e[j] = __expf(v[j] - mx); sum += e[j]; }
#pragma unroll
    for (int o = 16; o; o >>= 1) sum += __shfl_xor_sync(0xFFFFFFFFu, sum, o);
    if (lid == 0) sm2[wid] = sum;
    __syncthreads();
    sum = 0.f;
#pragma unroll
    for (int w = 0; w < 8; w++) sum += sm2[w];
    float inv = 1.0f / sum;
#pragma unroll
    for (int j = 0; j < 4; j++)
        g_attn[(size_t)(j * 256 + t) * B_DIM + b] = e[j] * inv;
}

// ---------------- Kernel 4a: output partials over s-blocks ----------------
__global__ void __launch_bounds__(256) output_part_kernel(const float* __restrict__ values) {
    __shared__ float sa[64 * 64];     // attn chunk [s2][b] (16 KB)
    const int t    = threadIdx.x;
    const int lane = t & 31;
    const int w    = t >> 5;          // warp 0..7
    const int b0   = w * 8;
    const int d    = blockIdx.x * 32 + lane;
    const int sbase = blockIdx.y * 64;

    float acc[8];
#pragma unroll
    for (int j = 0; j < 8; j++) acc[j] = 0.f;

    float4* sa4 = (float4*)sa;
    const float4* ga4 = (const float4*)(g_attn + (size_t)sbase * B_DIM);
#pragma unroll
    for (int j = 0; j < 4; j++) sa4[t + j * 256] = ga4[t + j * 256];
    __syncthreads();

    const float4* sarow = (const float4*)sa;
#pragma unroll 8
    for (int s2 = 0; s2 < 64; s2++) {
        float v = values[(size_t)(sbase + s2) * DV_DIM + d];
        float4 a01 = sarow[s2 * 16 + w * 2];
        float4 a23 = sarow[s2 * 16 + w * 2 + 1];
        acc[0] += a01.x * v; acc[1] += a01.y * v;
        acc[2] += a01.z * v; acc[3] += a01.w * v;
        acc[4] += a23.x * v; acc[5] += a23.y * v;
        acc[6] += a23.z * v; acc[7] += a23.w * v;
    }
#pragma unroll
    for (int j = 0; j < 8; j++)
        g_opart[((size_t)blockIdx.y * B_DIM + b0 + j) * DV_DIM + d] = acc[j];
}

// ---------------- Kernel 4b: reduce OSB s-block partials -> out ----------------
__global__ void __launch_bounds__(256) output_reduce_kernel(float* __restrict__ out) {
    int i = blockIdx.x * 256 + threadIdx.x;    // 16384 float4 over 64 CTAs
    const float4* p = (const float4*)g_opart;
    float4 r = p[i];
#pragma unroll
    for (int j = 1; j < OSB; j++) {
        float4 a = p[i + j * 16384];
        r.x += a.x; r.y += a.y; r.z += a.z; r.w += a.w;
    }
    ((float4*)out)[i] = r;
}

// ---------------- launch ----------------
extern "C" void kernel_launch(void* const* d_in, const int* in_sizes, int n_in,
                              void* d_out, int out_size) {
    const float* queries = (const float*)d_in[0];
    const float* keys    = (const float*)d_in[1];
    const float* values  = (const float*)d_in[2];
    const float* W_q     = (const float*)d_in[3];
    const float* W_k     = (const float*)d_in[4];
    const float* w_v     = (const float*)d_in[5];
    float* out = (float*)d_out;

    cudaFuncSetAttribute(gemm_scores_kernel,
                         cudaFuncAttributeMaxDynamicSharedMemorySize, SMEM_NEED);

    pack_W_kernel<<<256, 256>>>((const float4*)W_q, (const float4*)W_k);
    gemm_scores_kernel<<<dim3(4, M_TOT / MT), 256, SMEM_NEED>>>(queries, keys, w_v);
    softmax_kernel<<<B_DIM, 256>>>();
    output_part_kernel<<<dim3(32, OSB), 256>>>(values);
    output_reduce_kernel<<<64, 256>>>(out);
}

// round 12
// speedup vs baseline: 1.1809x; 1.1809x over previous
#include <cuda_runtime.h>
#include <cuda_fp16.h>
#include <cstdint>

// ---------------- problem dims ----------------
#define S_DIM 1024
#define B_DIM 64
#define M_TOT 65536           // S*B
#define QK_DIM 1024
#define KK 2048               // concatenated K = 2*QK
#define H_DIM 1024
#define DV_DIM 1024

// ---------------- GEMM tiling ----------------
#define MT 128
#define NT 256
#define KC 64                 // K halfs per stage
#define NSK (KK / KC)         // 32 k-stages
#define ROW_B 144             // smem row pitch bytes: 64 halfs + 8 pad halfs
#define A_BYTES (MT * ROW_B)             // 18432
#define B_BYTES (NT * ROW_B)             // 36864
#define STAGE_BYTES (A_BYTES + B_BYTES)  // 55296
#define SMEM_TILES_OFF 4096
#define SMEM_NEED (SMEM_TILES_OFF + 3 * STAGE_BYTES)   // 169984

#define OSB 32                // output s-blocks

// ---------------- device scratch (allocation-free) ----------------
__device__ __half g_W[(size_t)H_DIM * KK];    // packed [W_q|W_k] fp16 (4 MB)
__device__ float  g_part[4 * M_TOT];          // per-N-tile score partials
__device__ float  g_attn[M_TOT];
__device__ float  g_opart[OSB * B_DIM * DV_DIM]; // output partials (8 MB)

// ---------------- helpers ----------------
__device__ __forceinline__ uint32_t smem_u32(const void* p) {
    return (uint32_t)__cvta_generic_to_shared(p);
}

__device__ __forceinline__ void mma16816(float* c, const uint32_t* a, uint32_t b0, uint32_t b1) {
    asm volatile(
        "mma.sync.aligned.m16n8k16.row.col.f32.f16.f16.f32 "
        "{%0,%1,%2,%3}, {%4,%5,%6,%7}, {%8,%9}, {%0,%1,%2,%3};"
        : "+f"(c[0]), "+f"(c[1]), "+f"(c[2]), "+f"(c[3])
        : "r"(a[0]), "r"(a[1]), "r"(a[2]), "r"(a[3]), "r"(b0), "r"(b1));
}

__device__ __forceinline__ float fast_tanh(float x) {
    float y;
    asm("tanh.approx.f32 %0, %1;" : "=f"(y) : "f"(x));   // MUFU.TANH
    return y;
}

// ---------------- Kernel 1: pack [W_q|W_k] -> fp16 ----------------
__global__ void __launch_bounds__(256) pack_W_kernel(const float4* __restrict__ wq,
                                                     const float4* __restrict__ wk) {
    const size_t n4 = (size_t)H_DIM * QK_DIM / 4;
    for (size_t i = (size_t)blockIdx.x * blockDim.x + threadIdx.x; i < n4;
         i += (size_t)gridDim.x * blockDim.x) {
        size_t h = i >> 8;
        size_t c = (i & 255) << 2;
        float4 qa = wq[i];
        float4 ka = wk[i];
        union { __half2 h2[2]; uint2 u; } pq, pk;
        pq.h2[0] = __floats2half2_rn(qa.x, qa.y);
        pq.h2[1] = __floats2half2_rn(qa.z, qa.w);
        pk.h2[0] = __floats2half2_rn(ka.x, ka.y);
        pk.h2[1] = __floats2half2_rn(ka.z, ka.w);
        *(uint2*)(&g_W[h * KK + c])          = pq.u;
        *(uint2*)(&g_W[h * KK + QK_DIM + c]) = pk.u;
    }
}

// ---------------- Kernel 2: GEMM(features) + tanh + w_v reduce -> score partials ----------------
// 256 threads = 8 warps, warp layout 2m x 4n, warp tile 64 x 64. f32 accumulators.
__global__ void __launch_bounds__(256, 1)
gemm_scores_kernel(const float* __restrict__ queries,
                   const float* __restrict__ keys,
                   const float* __restrict__ w_v) {
    extern __shared__ char smem[];
    float* sWv   = (float*)smem;                 // 256 floats
    float* sPart = (float*)(smem + 1024);        // 4*128 floats
    char*  tiles = smem + SMEM_TILES_OFF;

    const int tid  = threadIdx.x;
    const int wid  = tid >> 5;
    const int lane = tid & 31;
    const int wm   = wid & 1;        // warp m index (0..1) -> 64 rows each
    const int wn   = wid >> 1;       // warp n index (0..3) -> 64 cols each
    const int nt   = blockIdx.x;     // N tile (0..3), fastest varying: A reuse in L2
    const int m0   = blockIdx.y * MT;
    const int h0   = nt * NT;

    sWv[tid] = w_v[h0 + tid];

    float acc[4][8][4];
#pragma unroll
    for (int mf = 0; mf < 4; mf++)
#pragma unroll
        for (int nf = 0; nf < 8; nf++)
#pragma unroll
            for (int i = 0; i < 4; i++) acc[mf][nf][i] = 0.f;

    const int ar = tid >> 4;              // A base row (rows step by 16 per j)
    const int ac = tid & 15;              // float4 col within 64-float k-chunk

    float4 pre[8];

    auto ldg_A = [&](int s) {
        const int kc = (s < 16) ? s * KC : (s - 16) * KC;
        const float* src = (s < 16) ? queries : keys;
#pragma unroll
        for (int j = 0; j < 8; j++) {
            int r = ar + j * 16;
            pre[j] = *(const float4*)(src + (size_t)(m0 + r) * QK_DIM + kc + ac * 4);
        }
    };
    auto sts_A = [&](int buf) {
        char* As = tiles + buf * STAGE_BYTES;
#pragma unroll
        for (int j = 0; j < 8; j++) {
            int r = ar + j * 16;
            union { __half2 h2[2]; uint2 u; } p;
            p.h2[0] = __floats2half2_rn(pre[j].x, pre[j].y);
            p.h2[1] = __floats2half2_rn(pre[j].z, pre[j].w);
            *(uint2*)(As + r * ROW_B + ac * 8) = p.u;
        }
    };
    auto cp_B = [&](int s, int buf) {
        char* Bs = tiles + buf * STAGE_BYTES + A_BYTES;
        const int k0 = s * KC;
#pragma unroll
        for (int j = 0; j < 8; j++) {
            int i = tid + j * 256;
            int r = i >> 3, c = i & 7;
            uint32_t sb = smem_u32(Bs + r * ROW_B + c * 16);
            size_t gb = (size_t)__cvta_generic_to_global(
                g_W + (size_t)(h0 + r) * KK + k0 + c * 8);
            asm volatile("cp.async.cg.shared.global [%0], [%1], 16;" :: "r"(sb), "l"(gb));
        }
        asm volatile("cp.async.commit_group;" ::: "memory");
    };

    auto compute_stage = [&](int buf) {
        char* As = tiles + buf * STAGE_BYTES;
        char* Bs = As + A_BYTES;
#pragma unroll
        for (int ks = 0; ks < 4; ks++) {     // four k16 steps per 64-half stage
            uint32_t a[4][4];
#pragma unroll
            for (int mf = 0; mf < 4; mf++) {
                int row = wm * 64 + mf * 16 + (lane & 7) + (lane & 8);
                int kb  = ks * 32 + ((lane >= 16) ? 16 : 0);
                uint32_t addr = smem_u32(As + row * ROW_B + kb);
                asm volatile(
                    "ldmatrix.sync.aligned.m8n8.x4.shared.b16 {%0,%1,%2,%3}, [%4];"
                    : "=r"(a[mf][0]), "=r"(a[mf][1]), "=r"(a[mf][2]), "=r"(a[mf][3])
                    : "r"(addr));
            }
#pragma unroll
            for (int np = 0; np < 4; np++) { // each x4 covers 2 n-frags
                uint32_t b[4];
                int rn = wn * 64 + np * 16 + (lane & 7) + ((lane >= 16) ? 8 : 0);
                int kb = ks * 32 + ((lane & 8) ? 16 : 0);
                uint32_t addr = smem_u32(Bs + rn * ROW_B + kb);
                asm volatile(
                    "ldmatrix.sync.aligned.m8n8.x4.shared.b16 {%0,%1,%2,%3}, [%4];"
                    : "=r"(b[0]), "=r"(b[1]), "=r"(b[2]), "=r"(b[3])
                    : "r"(addr));
#pragma unroll
                for (int mf = 0; mf < 4; mf++) {
                    mma16816(acc[mf][2 * np],     a[mf], b[0], b[1]);
                    mma16816(acc[mf][2 * np + 1], a[mf], b[2], b[3]);
                }
            }
        }
    };

    // ---- prologue: stages 0,1 in smem; stage 2 in registers ----
    ldg_A(0); sts_A(0); cp_B(0, 0);
    ldg_A(1); sts_A(1); cp_B(1, 1);
    ldg_A(2);

    // ---- main pipeline (3 smem buffers) ----
    for (int s = 0; s < NSK; s++) {
        if (s == NSK - 1) { asm volatile("cp.async.wait_group 0;" ::: "memory"); }
        else              { asm volatile("cp.async.wait_group 1;" ::: "memory"); }
        __syncthreads();
        if (s + 2 < NSK) {
            int buf = (s + 2) % 3;
            sts_A(buf);
            cp_B(s + 2, buf);
            if (s + 3 < NSK) ldg_A(s + 3);
        }
        compute_stage(s % 3);
    }

    // ---- epilogue: score_partial[m] = sum_h tanh(feat[m,h]) * w_v[h] ----
    float s0[4] = {0.f, 0.f, 0.f, 0.f}, s1[4] = {0.f, 0.f, 0.f, 0.f};
#pragma unroll
    for (int mf = 0; mf < 4; mf++) {
#pragma unroll
        for (int nf = 0; nf < 8; nf++) {
            int colb = wn * 64 + nf * 8 + 2 * (lane & 3);
            float wv0 = sWv[colb], wv1 = sWv[colb + 1];
            s0[mf] += fast_tanh(acc[mf][nf][0]) * wv0 + fast_tanh(acc[mf][nf][1]) * wv1;
            s1[mf] += fast_tanh(acc[mf][nf][2]) * wv0 + fast_tanh(acc[mf][nf][3]) * wv1;
        }
    }
#pragma unroll
    for (int mf = 0; mf < 4; mf++) {
#pragma unroll
        for (int o = 1; o <= 2; o <<= 1) {
            s0[mf] += __shfl_xor_sync(0xFFFFFFFFu, s0[mf], o);
            s1[mf] += __shfl_xor_sync(0xFFFFFFFFu, s1[mf], o);
        }
    }
    __syncthreads();
    if ((lane & 3) == 0) {
#pragma unroll
        for (int mf = 0; mf < 4; mf++) {
            int r = wm * 64 + mf * 16 + (lane >> 2);
            sPart[wn * 128 + r]     = s0[mf];
            sPart[wn * 128 + r + 8] = s1[mf];
        }
    }
    __syncthreads();
    if (tid < 128) {
        float tot = sPart[tid] + sPart[128 + tid] + sPart[256 + tid] + sPart[384 + tid];
        g_part[nt * M_TOT + m0 + tid] = tot;
    }
}

// ---------------- Kernel 3: softmax over S (per b column) ----------------
__global__ void __launch_bounds__(256) softmax_kernel() {
    int b = blockIdx.x, t = threadIdx.x;
    int wid = t >> 5, lid = t & 31;
    __shared__ float sm1[8], sm2[8];
    float v[4];
    float mx = -1e30f;
#pragma unroll
    for (int j = 0; j < 4; j++) {
        int m = (j * 256 + t) * B_DIM + b;
        v[j] = g_part[m] + g_part[M_TOT + m] + g_part[2 * M_TOT + m] + g_part[3 * M_TOT + m];
        mx = fmaxf(mx, v[j]);
    }
#pragma unroll
    for (int o = 16; o; o >>= 1) mx = fmaxf(mx, __shfl_xor_sync(0xFFFFFFFFu, mx, o));
    if (lid == 0) sm1[wid] = mx;
    __syncthreads();
    mx = sm1[0];
#pragma unroll
    for (int w = 1; w < 8; w++) mx = fmaxf(mx, sm1[w]);

    float e[4];
    float sum = 0.f;
#pragma unroll
    for (int j = 0; j < 4; j++) { e[j] = __expf(v[j] - mx); sum += e[j]; }
#pragma unroll
    for (int o = 16; o; o >>= 1) sum += __shfl_xor_sync(0xFFFFFFFFu, sum, o);
    if (lid == 0) sm2[wid] = sum;
    __syncthreads();
    sum = 0.f;
#pragma unroll
    for (int w = 0; w < 8; w++) sum += sm2[w];
    float inv = 1.0f / sum;
#pragma unroll
    for (int j = 0; j < 4; j++)
        g_attn[(size_t)(j * 256 + t) * B_DIM + b] = e[j] * inv;
}

// ---------------- Kernel 4a: output partials over s-blocks ----------------
// grid (32 d-blocks, 32 s-blocks), 256 thr. lane -> d (coalesced values LDG),
// warp -> 8 b's (register tile), 32-s attn chunk staged in smem.
__global__ void __launch_bounds__(256) output_part_kernel(const float* __restrict__ values) {
    __shared__ float sa[32 * 64];     // attn chunk [s2][b] (8 KB)
    const int t    = threadIdx.x;
    const int lane = t & 31;
    const int w    = t >> 5;          // warp 0..7
    const int b0   = w * 8;
    const int d    = blockIdx.x * 32 + lane;
    const int sbase = blockIdx.y * 32;

    float acc[8];
#pragma unroll
    for (int j = 0; j < 8; j++) acc[j] = 0.f;

    // stage attn[sbase..sbase+32)[0..64) : contiguous 2048 floats
    float4* sa4 = (float4*)sa;
    const float4* ga4 = (const float4*)(g_attn + (size_t)sbase * B_DIM);
#pragma unroll
    for (int j = 0; j < 2; j++) sa4[t + j * 256] = ga4[t + j * 256];
    __syncthreads();

    const float4* sarow = (const float4*)sa;
#pragma unroll 8
    for (int s2 = 0; s2 < 32; s2++) {
        float v = values[(size_t)(sbase + s2) * DV_DIM + d];
        float4 a01 = sarow[s2 * 16 + w * 2];
        float4 a23 = sarow[s2 * 16 + w * 2 + 1];
        acc[0] += a01.x * v; acc[1] += a01.y * v;
        acc[2] += a01.z * v; acc[3] += a01.w * v;
        acc[4] += a23.x * v; acc[5] += a23.y * v;
        acc[6] += a23.z * v; acc[7] += a23.w * v;
    }
#pragma unroll
    for (int j = 0; j < 8; j++)
        g_opart[((size_t)blockIdx.y * B_DIM + b0 + j) * DV_DIM + d] = acc[j];
}

// ---------------- Kernel 4b: reduce OSB s-block partials -> out ----------------
__global__ void __launch_bounds__(256) output_reduce_kernel(float* __restrict__ out) {
    int i = blockIdx.x * 256 + threadIdx.x;    // 16384 float4 over 64 CTAs
    const float4* p = (const float4*)g_opart;
    float4 r = p[i];
#pragma unroll
    for (int j = 1; j < OSB; j++) {
        float4 a = p[i + j * 16384];
        r.x += a.x; r.y += a.y; r.z += a.z; r.w += a.w;
    }
    ((float4*)out)[i] = r;
}

// ---------------- launch ----------------
extern "C" void kernel_launch(void* const* d_in, const int* in_sizes, int n_in,
                              void* d_out, int out_size) {
    const float* queries = (const float*)d_in[0];
    const float* keys    = (const float*)d_in[1];
    const float* values  = (const float*)d_in[2];
    const float* W_q     = (const float*)d_in[3];
    const float* W_k     = (const float*)d_in[4];
    const float* w_v     = (const float*)d_in[5];
    float* out = (float*)d_out;

    cudaFuncSetAttribute(gemm_scores_kernel,
                         cudaFuncAttributeMaxDynamicSharedMemorySize, SMEM_NEED);

    pack_W_kernel<<<256, 256>>>((const float4*)W_q, (const float4*)W_k);
    gemm_scores_kernel<<<dim3(4, M_TOT / MT), 256, SMEM_NEED>>>(queries, keys, w_v);
    softmax_kernel<<<B_DIM, 256>>>();
    output_part_kernel<<<dim3(32, OSB), 256>>>(values);
    output_reduce_kernel<<<64, 256>>>(out);
}